// round 3
// baseline (speedup 1.0000x reference)
#include <cuda_runtime.h>
#include <math.h>

// Problem constants
#define BN    64
#define HW    784          // 28*28
#define CN    512
#define S     14           // spatial splits (56*4B = 224 ≡ 0 mod 16 → float4-aligned)
#define HWP   56           // HW / S
#define HWP4  14           // HWP / 4
#define NT    (BN * S)     // 896 tiles per phase
#define GRID  444          // 148 SMs * 3 blocks (guaranteed by __launch_bounds__(512,3))

// Scratch for partial argmax results (device globals: allocation-free)
__device__ float g_pval[BN * S * CN];
__device__ int   g_pidx[BN * S * CN];

// Grid-wide barrier state (monotonic generation — safe across graph replays)
__device__ unsigned g_bar_count = 0;
__device__ unsigned g_bar_gen   = 0;

__device__ __forceinline__ void grid_barrier() {
    __syncthreads();
    if (threadIdx.x == 0) {
        __threadfence();                                   // release phase-1 writes
        unsigned my_gen  = atomicAdd(&g_bar_gen, 0u);      // read current generation
        unsigned arrived = atomicAdd(&g_bar_count, 1u);
        if (arrived == GRID - 1) {
            atomicExch(&g_bar_count, 0u);                  // reset for next replay
            __threadfence();
            atomicAdd(&g_bar_gen, 1u);                     // open the barrier
        } else {
            while (atomicAdd(&g_bar_gen, 0u) == my_gen) {} // spin (all CTAs resident)
        }
        __threadfence();                                   // acquire
    }
    __syncthreads();
}

// ---------------------------------------------------------------------------
// Fused persistent kernel.
// Phase 1: per-(b,c) partial argmax over 56-position spatial slices.
// Phase 2: combine 14 partials -> idx[b,c]; out = relu(x * t_p[b,idx,hw]).
// x (102.8MB) stays resident in L2 (~126MB) across the barrier; out uses
// streaming stores so it does not evict x.
// ---------------------------------------------------------------------------
__global__ void __launch_bounds__(512, 3)
fused_kernel(const float* __restrict__ x,
             const float* __restrict__ tp,
             float* __restrict__ out) {
    const int bid = blockIdx.x;
    const int c   = threadIdx.x;

    // ------------------ Phase 1: partial argmax ------------------
    for (int t = bid; t < NT; t += GRID) {
        const int b = t / S;
        const int s = t % S;

        const size_t base = ((size_t)b * HW + (size_t)s * HWP) * CN + c;

        float best = -INFINITY;
        int   bidx = s * HWP;

        #pragma unroll 8
        for (int i = 0; i < HWP; ++i) {
            float v = x[base + (size_t)i * CN];
            if (v > best) {          // strict > + ascending i => first occurrence
                best = v;
                bidx = s * HWP + i;
            }
        }

        const int o = (b * S + s) * CN + c;
        g_pval[o] = best;
        g_pidx[o] = bidx;
    }

    grid_barrier();

    // ------------------ Phase 2: combine + apply ------------------
    for (int t = bid; t < NT; t += GRID) {
        const int b = t / S;
        const int s = t % S;

        // Combine 14 partials: ascending split order + strict > keeps the
        // earliest spatial index on equal maxima (matches jnp.argmax).
        float best = -INFINITY;
        int   idx  = 0;
        #pragma unroll
        for (int p = 0; p < S; ++p) {
            const int o = (b * S + p) * CN + c;
            float v = g_pval[o];
            if (v > best) {
                best = v;
                idx  = g_pidx[o];
            }
        }

        // Selected template row slice: t_p[b, idx, s*56 .. s*56+55]
        // Row pitch 3136B and slice offset 224B are 16B multiples -> float4-safe.
        const float4* __restrict__ trow4 =
            (const float4*)(tp + ((size_t)b * HW + (size_t)idx) * HW + s * HWP);

        const size_t base = ((size_t)b * HW + (size_t)s * HWP) * CN + c;

        #pragma unroll 2
        for (int j = 0; j < HWP4; ++j) {
            const float4 t4 = __ldg(trow4 + j);
            const size_t o  = base + (size_t)(4 * j) * CN;

            float x0 = x[o];
            float x1 = x[o + (size_t)CN];
            float x2 = x[o + (size_t)(2 * CN)];
            float x3 = x[o + (size_t)(3 * CN)];

            // Streaming stores: evict-first, keep x resident in L2.
            __stcs(out + o,                    fmaxf(x0 * t4.x, 0.0f));
            __stcs(out + o + (size_t)CN,       fmaxf(x1 * t4.y, 0.0f));
            __stcs(out + o + (size_t)(2 * CN), fmaxf(x2 * t4.z, 0.0f));
            __stcs(out + o + (size_t)(3 * CN), fmaxf(x3 * t4.w, 0.0f));
        }
    }
}

// ---------------------------------------------------------------------------
// Launch: inputs [x, t_p]; output fp32 [64,28,28,512]. Single graph node.
// ---------------------------------------------------------------------------
extern "C" void kernel_launch(void* const* d_in, const int* in_sizes, int n_in,
                              void* d_out, int out_size) {
    (void)in_sizes; (void)n_in; (void)out_size;
    const float* x   = (const float*)d_in[0];
    const float* tp  = (const float*)d_in[1];
    float*       out = (float*)d_out;

    fused_kernel<<<GRID, CN>>>(x, tp, out);
}